// round 1
// baseline (speedup 1.0000x reference)
#include <cuda_runtime.h>

#define NE_   4096
#define LDIM_ 3
#define NP_   (NE_*LDIM_)   // 12288 independent (e,l) problems

// scratch for cross-energy delta combine (energy-axis reversal in reference)
static __device__ float g_lfin[NP_];
static __device__ float g_sin [NP_];
static __device__ float g_dout[NP_];
static __device__ float g_ui0 [NP_];
static __device__ float g_sout[NP_];

__device__ __forceinline__ float factor_at(int i, float ll1, float E) {
    // r = linspace(0.1, 100, 1000)[i]
    const float STEPF = (float)(99.9/999.0);
    const float R0F   = 0.1f;
    float r  = fmaf((float)i, STEPF, R0F);
    float rr = r*r;
    return ll1/rr + (-E - 1.0f/r);   // l(l+1)/r^2 + PARA1*(-E - 1/r), PARA1=1
}

__global__ void __launch_bounds__(128) solve_kernel(const float* __restrict__ energy_in,
                                                    float* __restrict__ out) {
    int idx = blockIdx.x*blockDim.x + threadIdx.x;
    if (idx >= NP_) return;
    int e = idx / LDIM_;
    int l = idx - e*LDIM_;
    float E  = energy_in[e];
    float lf = (float)l;
    float ll1 = lf*(lf+1.0f);

    const float C    = (float)(3.0/40.0*(0.1*0.1));   // 7.5e-4
    const float K1   = (float)(13.0/15.0*(0.1*0.1));
    const float K2   = (float)(7.0/60.0*(0.1*0.1));
    const float D12  = (float)(12.0*0.1);             // 1.2
    const float WINT = (float)(2.0*0.1/45.0);

    float* out_uz = out + NP_ + idx;                  // u_zero  block base (this problem)
    float* out_ui = out + NP_ + (size_t)100*NP_ + idx;// u_infty block base

    float u0,u1,u2,u3,u4;
    float acc4 = 0.0f, acc2 = 0.0f;

    // ======================= forward solve: u_zero (100 pts) =======================
    {
        float v[5];
        #pragma unroll
        for (int j = 0; j < 5; ++j) {
            float r0 = 0.1f*(float)(j+1);
            float p1 = r0;
            #pragma unroll
            for (int k = 0; k < 2; ++k) if (k < l) p1 *= r0;   // r0^(l+1)
            float p2 = p1*r0;                                   // r0^(l+2)
            v[j] = p1 - p2/(2.0f*(lf+1.0f));
            out_uz[(size_t)j*NP_] = v[j];
        }
        out_uz[(size_t)5*NP_] = v[4];   // duplicated window point u_zero[5]=pos4
        // integration weights for j=0..5 (func=u^2; g terms squared -> u^4, 12*g2 -> u^2)
        float q0=v[0]*v[0], q1=v[1]*v[1], q2=v[2]*v[2], q3=v[3]*v[3], q4=v[4]*v[4];
        acc4 = 7.0f*q0*q0 + 32.0f*q1*q1 + 32.0f*q3*q3 + 14.0f*q4*q4 + 32.0f*q4*q4;
        acc2 = 12.0f*q2;
        u0=v[0]; u1=v[1]; u2=v[2]; u3=v[3]; u4=v[4];
    }

    float f0 = factor_at(0,ll1,E);
    float f1 = factor_at(1,ll1,E);
    float f2 = factor_at(2,ll1,E);
    float f3 = factor_at(3,ll1,E);
    float f4 = factor_at(4,ll1,E);

    float* p_uz = out_uz + (size_t)6*NP_;
    #pragma unroll 4
    for (int p = 5; p <= 98; ++p) {
        float fn = factor_at(p, ll1, E);
        f0=f1; f1=f2; f2=f3; f3=f4; f4=fn;
        float denom = 1.0f - C*f4;
        float rden  = 1.0f/denom;
        float ca = fmaf(C *f0, rden, -1.0f);
        float cb = fmaf(K1*f1, rden,  2.0f);
        float cc = fmaf(K2*f2, rden, -2.0f);
        float cd = fmaf(K1*f3, rden,  2.0f);
        float nv = ((ca*u1 + cb*u2) + cc*u3) + cd*u4;
        *p_uz = nv; p_uz += NP_;
        int j = p + 1;                 // u_zero output index of this value
        if (j <= 96) {
            float q = nv*nv;
            int jm = j & 3;
            if (jm == 2) acc2 += 12.0f*q;
            else {
                float qq = q*q;
                float w = (jm == 0) ? ((j==96)?7.0f:14.0f) : 32.0f;
                acc4 += w*qq;
            }
        }
        u0=u1; u1=u2; u2=u3; u3=u4; u4=nv;
    }
    // last 5 positions 94..98 = u0..u4 ; u_zero[-1] = u4
    {
        float dnum = (25.0f*u4 - 48.0f*u3 + 36.0f*u2 - 16.0f*u1 + 3.0f*u0)/D12;
        g_lfin[idx] = dnum/u4;
        float integ_in = (acc4+acc2)*WINT;
        g_sin[idx] = integ_in/(u4*u4);
    }

    // ======================= reverse solve: u_infty (900 pts) =======================
    acc4 = 0.0f; acc2 = 0.0f;
    {
        float fact_l = (l==0)?1.0f:((l==1)?3.0f:15.0f);
        float se = sqrtf(fabsf(E));
        float v[5];
        #pragma unroll
        for (int j = 0; j < 5; ++j) {
            float rj = (float)(99.6 + 0.1*(double)j);
            float x  = rj*se;
            float xl = 1.0f;
            #pragma unroll
            for (int k = 0; k < 2; ++k) if (k < l) xl *= x;     // x^l
            float base = xl/fact_l;
            float x2h  = (x*x)*0.5f;
            float t1 = x2h/(2.0f*lf+3.0f);
            float t2 = (x2h*x2h)/(2.0f*(2.0f*lf+3.0f)*(2.0f*lf+5.0f));
            v[j] = rj*(base*(1.0f + t1 + t2));
        }
        out_ui[(size_t)899*NP_] = v[4];   // u_infty[899] = sol0[4]
        u0=v[0]; u1=v[1]; u2=v[2]; u3=v[3]; u4=v[4];
    }
    f0 = factor_at(999,ll1,E);
    f1 = factor_at(998,ll1,E);
    f2 = factor_at(997,ll1,E);
    f3 = factor_at(996,ll1,E);
    f4 = factor_at(995,ll1,E);

    float* p_ui = out_ui + (size_t)898*NP_;
    #pragma unroll 4
    for (int q = 5; q <= 898; ++q) {
        float fn = factor_at(999-q, ll1, E);
        f0=f1; f1=f2; f2=f3; f3=f4; f4=fn;
        float denom = 1.0f - C*f4;
        float rden  = 1.0f/denom;
        float ca = fmaf(C *f0, rden, -1.0f);
        float cb = fmaf(K1*f1, rden,  2.0f);
        float cc = fmaf(K2*f2, rden, -2.0f);
        float cd = fmaf(K1*f3, rden,  2.0f);
        float nv = ((ca*u1 + cb*u2) + cc*u3) + cd*u4;
        *p_ui = nv; p_ui -= NP_;
        int j = 903 - q;               // u_infty output index of this value
        if (j <= 896) {
            float qv = nv*nv;
            int jm = j & 3;
            if (jm == 2) acc2 += 12.0f*qv;
            else {
                float qq = qv*qv;
                float w = (jm == 0) ? ((j==896)?7.0f:14.0f) : 32.0f;
                acc4 += w*qq;
            }
        }
        u0=u1; u1=u2; u2=u3; u3=u4; u4=nv;
    }
    // final window positions 894..898 -> u_infty[0..4]
    out_ui[0]              = u0;
    out_ui[(size_t)1*NP_]  = u1;
    out_ui[(size_t)2*NP_]  = u2;
    out_ui[(size_t)3*NP_]  = u3;
    out_ui[(size_t)4*NP_]  = u4;
    {
        float q0=u0*u0, q1=u1*u1, q2v=u2*u2, q3=u3*u3, q4=u4*u4;
        acc4 += 7.0f*q0*q0 + 32.0f*q1*q1 + 32.0f*q3*q3 + 14.0f*q4*q4;
        acc2 += 12.0f*q2v;
        float dnum = (25.0f*u0 - 48.0f*u1 + 36.0f*u2 - 16.0f*u3 + 3.0f*u4)/D12;
        g_dout[idx] = dnum;
        g_ui0 [idx] = u0;
        float integ_out = (acc4+acc2)*WINT;
        g_sout[idx] = integ_out/(u0*u0);
    }
}

__global__ void __launch_bounds__(128) delta_kernel(const float* __restrict__ energy_in,
                                                    float* __restrict__ out) {
    int idx = blockIdx.x*blockDim.x + threadIdx.x;
    if (idx >= NP_) return;
    int e = idx / LDIM_;
    int l = idx - e*LDIM_;
    // reference: lfunc_out = _derivative(u_infty[::-1], ...)[::-1] / u_infty[0]
    //  -> numerator taken from energy index (NE-1-e), denominator from e
    float lfo = g_dout[(NE_-1-e)*LDIM_ + l] / g_ui0[idx];
    float delta = -(lfo - g_lfin[idx]) / (g_sin[idx] + g_sout[idx]);
    out[idx] = energy_in[e] + delta;
}

extern "C" void kernel_launch(void* const* d_in, const int* in_sizes, int n_in,
                              void* d_out, int out_size) {
    const float* init_energy = (const float*)d_in[0];
    float* out = (float*)d_out;
    (void)in_sizes; (void)n_in; (void)out_size;
    int threads = 128;
    int blocks  = (NP_ + threads - 1)/threads;   // 96
    solve_kernel<<<blocks, threads>>>(init_energy, out);
    delta_kernel<<<blocks, threads>>>(init_energy, out);
}

// round 2
// speedup vs baseline: 4.1882x; 4.1882x over previous
#include <cuda_runtime.h>

#define NE_   4096
#define LDIM_ 3
#define NP_   (NE_*LDIM_)   // 12288 independent (e,l) problems

// scratch for cross-energy delta combine (energy-axis reversal in reference)
static __device__ float g_lfin[NP_];
static __device__ float g_sin [NP_];
static __device__ float g_dout[NP_];
static __device__ float g_ui0 [NP_];
static __device__ float g_sout[NP_];

__device__ __forceinline__ float frcp(float x) {
    float y; asm("rcp.approx.f32 %0, %1;" : "=f"(y) : "f"(x)); return y;
}

__global__ void __launch_bounds__(128) solve_kernel(const float* __restrict__ energy_in,
                                                    float* __restrict__ out) {
    // 1/r and 1/r^2 are problem-independent: build once per block.
    __shared__ float2 s_r[1000];
    {
        int t = threadIdx.x;
        for (int i = t; i < 1000; i += 128) {
            float r    = fmaf((float)i, 0.1f, 0.1f);   // linspace(0.1,100,1000)
            float rinv = 1.0f / r;                      // precise, amortized
            s_r[i] = make_float2(rinv, rinv * rinv);
        }
    }
    __syncthreads();

    int idx = blockIdx.x*blockDim.x + threadIdx.x;
    if (idx >= NP_) return;
    int e = idx / LDIM_;
    int l = idx - e*LDIM_;
    float E  = energy_in[e];
    float lf = (float)l;
    float ll1 = lf*(lf+1.0f);
    float nE  = -E;

    const float C    = (float)(3.0/40.0*(0.1*0.1));   // 7.5e-4
    const float R1   = (float)(104.0/9.0);            // K1/C, K1 = 13/15*d^2
    const float R2   = (float)(14.0/9.0);             // K2/C, K2 = 7/60*d^2
    const float D12  = (float)(12.0*0.1);             // 1.2
    const float WINT = (float)(2.0*0.1/45.0);

    float* out_uz = out + NP_ + idx;                   // u_zero  block base
    float* out_ui = out + NP_ + (size_t)100*NP_ + idx; // u_infty block base

    float u0,u1,u2,u3,u4;
    float acc4 = 0.0f, acc2 = 0.0f;

    // factor(i) = ll1/r^2 - E - 1/r, scaled by C into shift registers
    #define CFACTOR(i) (C * (fmaf(ll1, s_r[(i)].y, nE) - s_r[(i)].x))

    // ======================= forward solve: u_zero (100 pts) =======================
    {
        float v[5];
        #pragma unroll
        for (int j = 0; j < 5; ++j) {
            float r0 = 0.1f*(float)(j+1);
            float p1 = r0;
            #pragma unroll
            for (int k = 0; k < 2; ++k) if (k < l) p1 *= r0;   // r0^(l+1)
            float p2 = p1*r0;                                   // r0^(l+2)
            v[j] = p1 - p2/(2.0f*(lf+1.0f));
            out_uz[(size_t)j*NP_] = v[j];
        }
        out_uz[(size_t)5*NP_] = v[4];   // duplicated window point u_zero[5]=pos4
        float q0=v[0]*v[0], q1=v[1]*v[1], q2=v[2]*v[2], q3=v[3]*v[3], q4=v[4]*v[4];
        acc4 = 7.0f*q0*q0 + 32.0f*q1*q1 + 32.0f*q3*q3 + 14.0f*q4*q4 + 32.0f*q4*q4;
        acc2 = 12.0f*q2;
        u0=v[0]; u1=v[1]; u2=v[2]; u3=v[3]; u4=v[4];
    }

    float cf0 = CFACTOR(0);
    float cf1 = CFACTOR(1);
    float cf2 = CFACTOR(2);
    float cf3 = CFACTOR(3);
    float cf4 = CFACTOR(4);

    float* p_uz = out_uz + (size_t)6*NP_;
    #pragma unroll 4
    for (int p = 5; p <= 98; ++p) {
        float cfn = CFACTOR(p);
        cf0=cf1; cf1=cf2; cf2=cf3; cf3=cf4; cf4=cfn;
        float rden = frcp(1.0f - cf4);
        float ca = fmaf(cf0,    rden, -1.0f);
        float cb = fmaf(R1*cf1, rden,  2.0f);
        float cc = fmaf(R2*cf2, rden, -2.0f);
        float cd = fmaf(R1*cf3, rden,  2.0f);
        float nv = ((ca*u1 + cb*u2) + cc*u3) + cd*u4;
        *p_uz = nv; p_uz += NP_;
        int j = p + 1;                 // u_zero output index of this value
        if (j <= 96) {
            float q = nv*nv;
            int jm = j & 3;
            if (jm == 2) acc2 = fmaf(12.0f, q, acc2);
            else {
                float qq = q*q;
                float w = (jm == 0) ? ((j==96)?7.0f:14.0f) : 32.0f;
                acc4 = fmaf(w, qq, acc4);
            }
        }
        u0=u1; u1=u2; u2=u3; u3=u4; u4=nv;
    }
    // last 5 positions 94..98 = u0..u4 ; u_zero[-1] = u4
    {
        float dnum = (25.0f*u4 - 48.0f*u3 + 36.0f*u2 - 16.0f*u1 + 3.0f*u0)/D12;
        g_lfin[idx] = dnum/u4;
        float integ_in = (acc4+acc2)*WINT;
        g_sin[idx] = integ_in/(u4*u4);
    }

    // ======================= reverse solve: u_infty (900 pts) =======================
    acc4 = 0.0f; acc2 = 0.0f;
    {
        float fact_l = (l==0)?1.0f:((l==1)?3.0f:15.0f);
        float se = sqrtf(fabsf(E));
        float v[5];
        #pragma unroll
        for (int j = 0; j < 5; ++j) {
            float rj = (float)(99.6 + 0.1*(double)j);
            float x  = rj*se;
            float xl = 1.0f;
            #pragma unroll
            for (int k = 0; k < 2; ++k) if (k < l) xl *= x;     // x^l
            float base = xl/fact_l;
            float x2h  = (x*x)*0.5f;
            float t1 = x2h/(2.0f*lf+3.0f);
            float t2 = (x2h*x2h)/(2.0f*(2.0f*lf+3.0f)*(2.0f*lf+5.0f));
            v[j] = rj*(base*(1.0f + t1 + t2));
        }
        out_ui[(size_t)899*NP_] = v[4];   // u_infty[899] = sol0[4]
        u0=v[0]; u1=v[1]; u2=v[2]; u3=v[3]; u4=v[4];
    }
    cf0 = CFACTOR(999);
    cf1 = CFACTOR(998);
    cf2 = CFACTOR(997);
    cf3 = CFACTOR(996);
    cf4 = CFACTOR(995);

    float* p_ui = out_ui + (size_t)898*NP_;
    #pragma unroll 4
    for (int q = 5; q <= 898; ++q) {
        float cfn = CFACTOR(999 - q);
        cf0=cf1; cf1=cf2; cf2=cf3; cf3=cf4; cf4=cfn;
        float rden = frcp(1.0f - cf4);
        float ca = fmaf(cf0,    rden, -1.0f);
        float cb = fmaf(R1*cf1, rden,  2.0f);
        float cc = fmaf(R2*cf2, rden, -2.0f);
        float cd = fmaf(R1*cf3, rden,  2.0f);
        float nv = ((ca*u1 + cb*u2) + cc*u3) + cd*u4;
        *p_ui = nv; p_ui -= NP_;
        int j = 903 - q;               // u_infty output index of this value
        if (j <= 896) {
            float qv = nv*nv;
            int jm = j & 3;
            if (jm == 2) acc2 = fmaf(12.0f, qv, acc2);
            else {
                float qq = qv*qv;
                float w = (jm == 0) ? ((j==896)?7.0f:14.0f) : 32.0f;
                acc4 = fmaf(w, qq, acc4);
            }
        }
        u0=u1; u1=u2; u2=u3; u3=u4; u4=nv;
    }
    // final window positions 894..898 -> u_infty[0..4]
    out_ui[0]              = u0;
    out_ui[(size_t)1*NP_]  = u1;
    out_ui[(size_t)2*NP_]  = u2;
    out_ui[(size_t)3*NP_]  = u3;
    out_ui[(size_t)4*NP_]  = u4;
    {
        float q0=u0*u0, q1=u1*u1, q2v=u2*u2, q3=u3*u3, q4=u4*u4;
        acc4 += 7.0f*q0*q0 + 32.0f*q1*q1 + 32.0f*q3*q3 + 14.0f*q4*q4;
        acc2 += 12.0f*q2v;
        float dnum = (25.0f*u0 - 48.0f*u1 + 36.0f*u2 - 16.0f*u3 + 3.0f*u4)/D12;
        g_dout[idx] = dnum;
        g_ui0 [idx] = u0;
        float integ_out = (acc4+acc2)*WINT;
        g_sout[idx] = integ_out/(u0*u0);
    }
    #undef CFACTOR
}

__global__ void __launch_bounds__(128) delta_kernel(const float* __restrict__ energy_in,
                                                    float* __restrict__ out) {
    int idx = blockIdx.x*blockDim.x + threadIdx.x;
    if (idx >= NP_) return;
    int e = idx / LDIM_;
    int l = idx - e*LDIM_;
    // reference: lfunc_out = _derivative(u_infty[::-1], ...)[::-1] / u_infty[0]
    //  -> numerator taken from energy index (NE-1-e), denominator from e
    float lfo = g_dout[(NE_-1-e)*LDIM_ + l] / g_ui0[idx];
    float delta = -(lfo - g_lfin[idx]) / (g_sin[idx] + g_sout[idx]);
    out[idx] = energy_in[e] + delta;
}

extern "C" void kernel_launch(void* const* d_in, const int* in_sizes, int n_in,
                              void* d_out, int out_size) {
    const float* init_energy = (const float*)d_in[0];
    float* out = (float*)d_out;
    (void)in_sizes; (void)n_in; (void)out_size;
    int threads = 128;
    int blocks  = (NP_ + threads - 1)/threads;   // 96
    solve_kernel<<<blocks, threads>>>(init_energy, out);
    delta_kernel<<<blocks, threads>>>(init_energy, out);
}

// round 3
// speedup vs baseline: 9.2172x; 2.2008x over previous
#include <cuda_runtime.h>

#define NE_ 4096
#define L3_ 3
#define NP_ 12288

__global__ void __launch_bounds__(128) eval_kernel(const float* __restrict__ energy_in,
                                                   float* __restrict__ out) {
    // per-l radial table with C folded: s_g[l][i] = C*(l(l+1)/r^2 - 1/r), r = 0.1*(i+1)
    __shared__ float s_g[3 * 1000];
    {
        const float C = 7.5e-4f;   // 3/40 * 0.1^2
        for (int i = threadIdx.x; i < 1000; i += 128) {
            float r   = fmaf((float)i, 0.1f, 0.1f);
            float y   = 1.0f / r;           // precise, amortized
            float cy  = C * y;              // C/r
            float cy2 = cy * y;             // C/r^2
            s_g[i]        = -cy;
            s_g[1000 + i] = fmaf(2.0f, cy2, -cy);
            s_g[2000 + i] = fmaf(6.0f, cy2, -cy);
        }
    }
    __syncthreads();

    // lane pairing: tau and tau^1 handle mirror energies (e, NE-1-e), same l
    int tau = blockIdx.x * 128 + threadIdx.x;
    int h   = tau >> 1;
    int s_  = tau & 1;
    int ep  = h / 3;
    int l   = h - ep * 3;
    int e   = s_ ? (NE_ - 1 - ep) : ep;
    int idx = e * 3 + l;

    float E  = energy_in[e];
    float lf = (float)l;
    const float C   = 7.5e-4f;
    float CE = C * E;
    const float* gl = &s_g[l * 1000];
    #define CF(i) (gl[(i)] - CE)

    const float R1c  = (float)(104.0 / 9.0);   // (13/15*d^2)/C
    const float R2c  = (float)(14.0 / 9.0);    // (7/60*d^2)/C
    const float WINT = (float)(2.0 * 0.1 / 45.0);
    const float DRCP = (float)(1.0 / 1.2);

    float* out_uz = out + NP_ + idx;
    float* out_ui = out + NP_ + (size_t)100 * NP_ + idx;

    float u0, u1, u2, u3, u4;
    float acc4, acc2;

    // one recurrence step: nv = rden*s + base, rden = (1+x)(1+x^2)
    #define STEP(A,B,CC,D,X, STADDR, WCODE) do {                 \
        float t1 = (B) * u2;  t1 = fmaf((D), u4, t1);            \
        float r3 = R2c * u3;                                     \
        float t2 = (A) * u1;  t2 = fmaf((CC), r3, t2);           \
        float sv = fmaf(R1c, t1, t2);                            \
        float bt = u2 - u3;   bt = bt + u4;                      \
        float bs = fmaf(2.0f, bt, -u1);                          \
        float xx = (X);                                          \
        float x2 = xx * xx;                                      \
        float hh = fmaf(xx, sv, sv);                             \
        float rs = fmaf(x2, hh, hh);                             \
        float nv = rs + bs;                                      \
        *(STADDR) = nv;                                          \
        WCODE;                                                   \
        u0 = u1; u1 = u2; u2 = u3; u3 = u4; u4 = nv;             \
    } while (0)

    #define I14 { float q = u4*u4; float qq = q*q; acc4 = fmaf(14.0f, qq, acc4); }
    #define I32 { float q = u4*u4; float qq = q*q; acc4 = fmaf(32.0f, qq, acc4); }
    #define I12 { float q = u4*u4; acc2 = fmaf(12.0f, q, acc2); }
    #define I7  { float q = u4*u4; float qq = q*q; acc4 = fmaf(7.0f,  qq, acc4); }
    #define I0  { }
    // note: WCODE runs AFTER the shift would be wrong; it must use nv. Use u4? shift is after WCODE?
    // WCODE placed before shift in STEP, so reference nv via local: adjust below.
    #undef I14
    #undef I32
    #undef I12
    #undef I7
    #undef STEP
    #define STEP(A,B,CC,D,X, STADDR, WCODE) do {                 \
        float t1 = (B) * u2;  t1 = fmaf((D), u4, t1);            \
        float r3 = R2c * u3;                                     \
        float t2 = (A) * u1;  t2 = fmaf((CC), r3, t2);           \
        float sv = fmaf(R1c, t1, t2);                            \
        float bt = u2 - u3;   bt = bt + u4;                      \
        float bs = fmaf(2.0f, bt, -u1);                          \
        float xx = (X);                                          \
        float x2 = xx * xx;                                      \
        float hh = fmaf(xx, sv, sv);                             \
        float rs = fmaf(x2, hh, hh);                             \
        float nv = rs + bs;                                      \
        *(STADDR) = nv;                                          \
        { float q = nv * nv; WCODE; }                            \
        u0 = u1; u1 = u2; u2 = u3; u3 = u4; u4 = nv;             \
    } while (0)
    #define W14 { float qq = q*q; acc4 = fmaf(14.0f, qq, acc4); }
    #define W32 { float qq = q*q; acc4 = fmaf(32.0f, qq, acc4); }
    #define W12 { acc2 = fmaf(12.0f, q, acc2); }
    #define W7  { float qq = q*q; acc4 = fmaf(7.0f,  qq, acc4); }
    #define W0  { (void)q; }

    float dnf, lfin, s_in;

    // ======================= forward: u_zero (100 pts) =======================
    {
        float v0, v1, v2, v3, v4;
        {
            float inv2l1 = 1.0f / (2.0f * (lf + 1.0f));
            #pragma unroll
            for (int j = 0; j < 5; ++j) {
                float r0 = 0.1f * (float)(j + 1);
                float p1 = r0;
                if (l >= 1) p1 *= r0;
                if (l >= 2) p1 *= r0;
                float val = p1 - (p1 * r0) * inv2l1;
                out_uz[(size_t)j * NP_] = val;
                if (j == 0) v0 = val; else if (j == 1) v1 = val;
                else if (j == 2) v2 = val; else if (j == 3) v3 = val; else v4 = val;
            }
        }
        out_uz[(size_t)5 * NP_] = v4;   // duplicated window point
        float q0 = v0*v0, q1 = v1*v1, q2 = v2*v2, q3 = v3*v3, q4 = v4*v4;
        acc4 = 7.0f*q0*q0 + 32.0f*q1*q1 + 32.0f*q3*q3 + 14.0f*q4*q4 + 32.0f*q4*q4;
        acc2 = 12.0f*q2;
        u0 = v0; u1 = v1; u2 = v2; u3 = v3; u4 = v4;
    }

    {
        float f0 = CF(0), f1 = CF(1), f2 = CF(2), f3 = CF(3), f4 = CF(4);
        // peel p=5..10 (j=6..11): weights 12,32,14,32,12,32
        { float fn=CF(5);  f0=f1; f1=f2; f2=f3; f3=f4; f4=fn; STEP(f0,f1,f2,f3,f4, out_uz+(size_t)6*NP_,  W12); }
        { float fn=CF(6);  f0=f1; f1=f2; f2=f3; f3=f4; f4=fn; STEP(f0,f1,f2,f3,f4, out_uz+(size_t)7*NP_,  W32); }
        { float fn=CF(7);  f0=f1; f1=f2; f2=f3; f3=f4; f4=fn; STEP(f0,f1,f2,f3,f4, out_uz+(size_t)8*NP_,  W14); }
        { float fn=CF(8);  f0=f1; f1=f2; f2=f3; f3=f4; f4=fn; STEP(f0,f1,f2,f3,f4, out_uz+(size_t)9*NP_,  W32); }
        { float fn=CF(9);  f0=f1; f1=f2; f2=f3; f3=f4; f4=fn; STEP(f0,f1,f2,f3,f4, out_uz+(size_t)10*NP_, W12); }
        { float fn=CF(10); f0=f1; f1=f2; f2=f3; f3=f4; f4=fn; STEP(f0,f1,f2,f3,f4, out_uz+(size_t)11*NP_, W32); }
        // window now CF(6..10); groups p0=11..95 need c0..c7 = CF(7..14)
        float c0 = f1, c1 = f2, c2 = f3, c3 = f4;
        float c4 = CF(11), c5 = CF(12), c6 = CF(13), c7 = CF(14);

        float* pf = out_uz + (size_t)12 * NP_;
        int pi = 15;
        #pragma unroll 1
        for (int g = 0; g < 22; ++g) {
            float n0 = CF(pi), n1 = CF(pi+1), n2 = CF(pi+2), n3 = CF(pi+3);
            pi += 4;
            STEP(c0,c1,c2,c3,c4, pf,                 W14);
            STEP(c1,c2,c3,c4,c5, pf + NP_,           W32);
            STEP(c2,c3,c4,c5,c6, pf + 2*(size_t)NP_, W12);
            STEP(c3,c4,c5,c6,c7, pf + 3*(size_t)NP_, W32);
            c0 = c4; c1 = c5; c2 = c6; c3 = c7;
            c4 = n0; c5 = n1; c6 = n2; c7 = n3;
            pf += 4 * (size_t)NP_;
        }
    }
    // end state u0..u4 = j95..99
    {
        dnf  = (25.0f*u4 - 48.0f*u3 + 36.0f*u2 - 16.0f*u1 + 3.0f*u0) * DRCP;
        lfin = dnf / u4;
        // corrections: j96 14->7, j97/j98/j99 excluded
        float q1 = u1*u1, q2 = u2*u2, q3 = u3*u3, q4 = u4*u4;
        acc4 -= 7.0f*(q1*q1) + 32.0f*(q2*q2) + 32.0f*(q4*q4);
        acc2 -= 12.0f*q3;
        float integ_in = (acc4 + acc2) * WINT;
        s_in = integ_in / (u4 * u4);
    }

    // ======================= reverse: u_infty (900 pts) =======================
    acc4 = 0.0f; acc2 = 0.0f;
    {
        float fact_l = (l == 0) ? 1.0f : ((l == 1) ? 3.0f : 15.0f);
        float se = sqrtf(fabsf(E));
        float i3 = 1.0f / (2.0f*lf + 3.0f);
        float i35 = 1.0f / (2.0f*(2.0f*lf + 3.0f)*(2.0f*lf + 5.0f));
        float v0, v1, v2, v3, v4;
        #pragma unroll
        for (int j = 0; j < 5; ++j) {
            float rj = (float)(99.6 + 0.1 * (double)j);
            float x  = rj * se;
            float xl = 1.0f;
            if (l >= 1) xl *= x;
            if (l >= 2) xl *= x;
            float base = xl / fact_l;
            float x2h  = (x*x) * 0.5f;
            float t1 = x2h * i3;
            float t2 = (x2h*x2h) * i35;
            float val = rj * (base * (1.0f + t1 + t2));
            if (j == 0) v0 = val; else if (j == 1) v1 = val;
            else if (j == 2) v2 = val; else if (j == 3) v3 = val; else v4 = val;
        }
        out_ui[(size_t)899 * NP_] = v4;
        u0 = v0; u1 = v1; u2 = v2; u3 = v3; u4 = v4;
    }
    {
        float f0 = CF(999), f1 = CF(998), f2 = CF(997), f3 = CF(996), f4 = CF(995);
        // peel q=5..10 (j=898..893): weights 0,0,7,32,12,32
        { float fn=CF(994); f0=f1; f1=f2; f2=f3; f3=f4; f4=fn; STEP(f0,f1,f2,f3,f4, out_ui+(size_t)898*NP_, W0 ); }
        { float fn=CF(993); f0=f1; f1=f2; f2=f3; f3=f4; f4=fn; STEP(f0,f1,f2,f3,f4, out_ui+(size_t)897*NP_, W0 ); }
        { float fn=CF(992); f0=f1; f1=f2; f2=f3; f3=f4; f4=fn; STEP(f0,f1,f2,f3,f4, out_ui+(size_t)896*NP_, W7 ); }
        { float fn=CF(991); f0=f1; f1=f2; f2=f3; f3=f4; f4=fn; STEP(f0,f1,f2,f3,f4, out_ui+(size_t)895*NP_, W32); }
        { float fn=CF(990); f0=f1; f1=f2; f2=f3; f3=f4; f4=fn; STEP(f0,f1,f2,f3,f4, out_ui+(size_t)894*NP_, W12); }
        { float fn=CF(989); f0=f1; f1=f2; f2=f3; f3=f4; f4=fn; STEP(f0,f1,f2,f3,f4, out_ui+(size_t)893*NP_, W32); }
        // window now CF(993..989); groups q0=11..895 need c0..c7 = CF(992..985)
        float c0 = f1, c1 = f2, c2 = f3, c3 = f4;
        float c4 = CF(988), c5 = CF(987), c6 = CF(986), c7 = CF(985);

        float* pr = out_ui + (size_t)889 * NP_;   // q0=11: stores j=892..889 at +3,+2,+1,+0
        int ri = 984;
        #pragma unroll 1
        for (int g = 0; g < 222; ++g) {
            float n0 = CF(ri), n1 = CF(ri-1), n2 = CF(ri-2), n3 = CF(ri-3);
            ri -= 4;
            STEP(c0,c1,c2,c3,c4, pr + 3*(size_t)NP_, W14);
            STEP(c1,c2,c3,c4,c5, pr + 2*(size_t)NP_, W32);
            STEP(c2,c3,c4,c5,c6, pr + NP_,           W12);
            STEP(c3,c4,c5,c6,c7, pr,                 W32);
            c0 = c4; c1 = c5; c2 = c6; c3 = c7;
            c4 = n0; c5 = n1; c6 = n2; c7 = n3;
            pr -= 4 * (size_t)NP_;
        }
    }
    // end state: u4=j5 ... u0=j9; reference places final window at u_infty[0..4]
    out_ui[0]               = u0;
    out_ui[(size_t)1 * NP_] = u1;
    out_ui[(size_t)2 * NP_] = u2;
    out_ui[(size_t)3 * NP_] = u3;
    out_ui[(size_t)4 * NP_] = u4;
    {
        float q0 = u0*u0, q1 = u1*u1, q2 = u2*u2, q3 = u3*u3, q4 = u4*u4;
        acc4 += 7.0f*(q0*q0) + 32.0f*(q1*q1) + 32.0f*(q3*q3) + 14.0f*(q4*q4);
        acc2 += 12.0f*q2;
        float dnr = (25.0f*u0 - 48.0f*u1 + 36.0f*u2 - 16.0f*u3 + 3.0f*u4) * DRCP;
        float integ_out = (acc4 + acc2) * WINT;
        float s_out = integ_out / (u0 * u0);

        // delta combine: mirror-energy derivative from paired lane
        float dnm = __shfl_xor_sync(0xffffffffu, dnr, 1);
        float lfo = dnm / u0;
        float delta = -(lfo - lfin) / (s_in + s_out);
        out[idx] = E + delta;
    }
    #undef STEP
    #undef CF
}

extern "C" void kernel_launch(void* const* d_in, const int* in_sizes, int n_in,
                              void* d_out, int out_size) {
    const float* init_energy = (const float*)d_in[0];
    float* out = (float*)d_out;
    (void)in_sizes; (void)n_in; (void)out_size;
    eval_kernel<<<NP_ / 128, 128>>>(init_energy, out);
}

// round 4
// speedup vs baseline: 9.2522x; 1.0038x over previous
#include <cuda_runtime.h>

#define NE_ 4096
#define NP_ 12288

__global__ void __launch_bounds__(128) eval_kernel(const float* __restrict__ energy_in,
                                                   float* __restrict__ out) {
    // per-l radial table with C folded: s_g[l][i] = C*(l(l+1)/r^2 - 1/r), r = 0.1*(i+1)
    __shared__ float s_g[3 * 1000];
    {
        const float C = 7.5e-4f;   // 3/40 * 0.1^2
        for (int i = threadIdx.x; i < 1000; i += 128) {
            float r   = fmaf((float)i, 0.1f, 0.1f);
            float y   = 1.0f / r;           // precise, amortized
            float cy  = C * y;
            float cy2 = cy * y;
            s_g[i]        = -cy;
            s_g[1000 + i] = fmaf(2.0f, cy2, -cy);
            s_g[2000 + i] = fmaf(6.0f, cy2, -cy);
        }
    }
    __syncthreads();

    // lane pairing: tau and tau^1 handle mirror energies (e, NE-1-e), same l
    int tau = blockIdx.x * 128 + threadIdx.x;
    int h   = tau >> 1;
    int s_  = tau & 1;
    int ep  = h / 3;
    int l   = h - ep * 3;
    int e   = s_ ? (NE_ - 1 - ep) : ep;
    int idx = e * 3 + l;

    float E  = energy_in[e];
    float lf = (float)l;
    const float C = 7.5e-4f;
    float CE = C * E;
    const float* gl = &s_g[l * 1000];
    #define CF(i) (gl[(i)] - CE)

    const float R1c  = (float)(104.0 / 9.0);   // (13/15*d^2)/C
    const float R2c  = (float)(14.0 / 9.0);    // (7/60*d^2)/C
    const float WINT = (float)(2.0 * 0.1 / 45.0);
    const float DRCP = (float)(1.0 / 1.2);

    float* out_uz = out + NP_ + idx;
    float* out_ui = out + NP_ + (size_t)100 * NP_ + idx;

    float u0, u1, u2, u3, u4;
    float acc4, acc2;

    // coefficient-dot step: nv = ca*u1+cb*u2+cc*u3+cd*u4,
    // ca=fma(CA,R,-1) cb=fma(CB,R,2) cc=fma(CC,R,-2) cd=fma(CD,R,2)
    // where CA=cf(p-4), CB=R1c*cf(p-3), CC=R2c*cf(p-2), CD=R1c*cf(p-1), R from x=cf(p).
    #define DOT_STEP(CA,CB,CC,CD, RR, STADDR, WCODE) do {        \
        float ka = fmaf((CA), (RR), -1.0f);                      \
        float kb = fmaf((CB), (RR),  2.0f);                      \
        float kc = fmaf((CC), (RR), -2.0f);                      \
        float kd = fmaf((CD), (RR),  2.0f);                      \
        float tt = ka * u1;                                      \
        tt = fmaf(kb, u2, tt);                                   \
        tt = fmaf(kc, u3, tt);                                   \
        float nv = fmaf(kd, u4, tt);                             \
        *(STADDR) = nv;                                          \
        { float q = nv * nv; WCODE; }                            \
        u0 = u1; u1 = u2; u2 = u3; u3 = u4; u4 = nv;             \
    } while (0)

    #define W14 { float qq = q*q; acc4 = fmaf(14.0f, qq, acc4); }
    #define W32 { float qq = q*q; acc4 = fmaf(32.0f, qq, acc4); }
    #define W12 { acc2 = fmaf(12.0f, q, acc2); }
    #define W7  { float qq = q*q; acc4 = fmaf(7.0f,  qq, acc4); }
    #define W0  { (void)q; }

    // peel step with raw cf shift registers pf0..pf4
    #define PEEL_STEP(NEWCF, STADDR, WCODE) do {                 \
        float fn = (NEWCF);                                      \
        pf0 = pf1; pf1 = pf2; pf2 = pf3; pf3 = pf4; pf4 = fn;    \
        float ee = pf4 + 1.0f;                                   \
        float gg = fmaf(pf4, pf4, 1.0f);                         \
        float RR = ee * gg;                                      \
        DOT_STEP(pf0, R1c*pf1, R2c*pf2, R1c*pf3, RR, STADDR, WCODE); \
    } while (0)

    float lfin, s_in;

    // ======================= forward: u_zero (100 pts) =======================
    {
        float v0, v1, v2, v3, v4;
        {
            float inv2l1 = 1.0f / (2.0f * (lf + 1.0f));
            #pragma unroll
            for (int j = 0; j < 5; ++j) {
                float r0 = 0.1f * (float)(j + 1);
                float p1 = r0;
                if (l >= 1) p1 *= r0;
                if (l >= 2) p1 *= r0;
                float val = p1 - (p1 * r0) * inv2l1;
                out_uz[(size_t)j * NP_] = val;
                if (j == 0) v0 = val; else if (j == 1) v1 = val;
                else if (j == 2) v2 = val; else if (j == 3) v3 = val; else v4 = val;
            }
        }
        out_uz[(size_t)5 * NP_] = v4;   // duplicated window point
        float q0 = v0*v0, q1 = v1*v1, q2 = v2*v2, q3 = v3*v3, q4 = v4*v4;
        acc4 = 7.0f*q0*q0 + 32.0f*q1*q1 + 32.0f*q3*q3 + 14.0f*q4*q4 + 32.0f*q4*q4;
        acc2 = 12.0f*q2;
        u0 = v0; u1 = v1; u2 = v2; u3 = v3; u4 = v4;
    }

    {
        float pf0 = CF(0), pf1 = CF(1), pf2 = CF(2), pf3 = CF(3), pf4 = CF(4);
        // peel p=5..10 (j=6..11): weights 12,32,14,32,12,32
        PEEL_STEP(CF(5),  out_uz + (size_t)6*NP_,  W12);
        PEEL_STEP(CF(6),  out_uz + (size_t)7*NP_,  W32);
        PEEL_STEP(CF(7),  out_uz + (size_t)8*NP_,  W14);
        PEEL_STEP(CF(8),  out_uz + (size_t)9*NP_,  W32);
        PEEL_STEP(CF(9),  out_uz + (size_t)10*NP_, W12);
        PEEL_STEP(CF(10), out_uz + (size_t)11*NP_, W32);
        // lanes for steady groups starting p0=11: indices 7..14
        float f0 = pf1, f1 = pf2, f2 = pf3, f3 = pf4;
        float f4 = CF(11), f5 = CF(12), f6 = CF(13), f7 = CF(14);
        float a0 = R1c*f0, a1 = R1c*f1, a2 = R1c*f2, a3 = R1c*f3;
        float a4 = R1c*f4, a5 = R1c*f5, a6 = R1c*f6, a7 = R1c*f7;
        float b0 = R2c*f0, b1 = R2c*f1, b2 = R2c*f2, b3 = R2c*f3;
        float b4 = R2c*f4, b5 = R2c*f5, b6 = R2c*f6, b7 = R2c*f7;
        (void)a0; (void)b0; (void)b1;

        float* pfp = out_uz + (size_t)12 * NP_;
        int pi = 15;
        #pragma unroll 1
        for (int g = 0; g < 22; ++g) {
            float n0 = CF(pi), n1 = CF(pi+1), n2 = CF(pi+2), n3 = CF(pi+3);
            pi += 4;
            float na0 = R1c*n0, na1 = R1c*n1, na2 = R1c*n2, na3 = R1c*n3;
            float nb0 = R2c*n0, nb1 = R2c*n1, nb2 = R2c*n2, nb3 = R2c*n3;
            float e0 = f4+1.0f, g0_ = fmaf(f4,f4,1.0f), r0 = e0*g0_;
            float e1 = f5+1.0f, g1_ = fmaf(f5,f5,1.0f), r1 = e1*g1_;
            float e2 = f6+1.0f, g2_ = fmaf(f6,f6,1.0f), r2 = e2*g2_;
            float e3 = f7+1.0f, g3_ = fmaf(f7,f7,1.0f), r3 = e3*g3_;
            DOT_STEP(f0, a1, b2, a3, r0, pfp,                 W14);
            DOT_STEP(f1, a2, b3, a4, r1, pfp + NP_,           W32);
            DOT_STEP(f2, a3, b4, a5, r2, pfp + 2*(size_t)NP_, W12);
            DOT_STEP(f3, a4, b5, a6, r3, pfp + 3*(size_t)NP_, W32);
            f0 = f4; f1 = f5; f2 = f6; f3 = f7; f4 = n0; f5 = n1; f6 = n2; f7 = n3;
            a1 = a5; a2 = a6; a3 = a7; a4 = na0; a5 = na1; a6 = na2; a7 = na3;
            b2 = b6; b3 = b7; b4 = nb0; b5 = nb1; b6 = nb2; b7 = nb3;
            pfp += 4 * (size_t)NP_;
        }
    }
    // end state u0..u4 = j95..99
    {
        float dnf = (25.0f*u4 - 48.0f*u3 + 36.0f*u2 - 16.0f*u1 + 3.0f*u0) * DRCP;
        lfin = dnf / u4;
        // corrections: j96 14->7; j97/j98/j99 excluded
        float q1 = u1*u1, q2 = u2*u2, q3 = u3*u3, q4 = u4*u4;
        acc4 -= 7.0f*(q1*q1) + 32.0f*(q2*q2) + 32.0f*(q4*q4);
        acc2 -= 12.0f*q3;
        float integ_in = (acc4 + acc2) * WINT;
        s_in = integ_in / (u4 * u4);
    }

    // ======================= reverse: u_infty (900 pts) =======================
    acc4 = 0.0f; acc2 = 0.0f;
    {
        float fact_l = (l == 0) ? 1.0f : ((l == 1) ? 3.0f : 15.0f);
        float se = sqrtf(fabsf(E));
        float i3  = 1.0f / (2.0f*lf + 3.0f);
        float i35 = 1.0f / (2.0f*(2.0f*lf + 3.0f)*(2.0f*lf + 5.0f));
        float v0, v1, v2, v3, v4;
        #pragma unroll
        for (int j = 0; j < 5; ++j) {
            float rj = (float)(99.6 + 0.1 * (double)j);
            float x  = rj * se;
            float xl = 1.0f;
            if (l >= 1) xl *= x;
            if (l >= 2) xl *= x;
            float base = xl / fact_l;
            float x2h  = (x*x) * 0.5f;
            float t1 = x2h * i3;
            float t2 = (x2h*x2h) * i35;
            float val = rj * (base * (1.0f + t1 + t2));
            if (j == 0) v0 = val; else if (j == 1) v1 = val;
            else if (j == 2) v2 = val; else if (j == 3) v3 = val; else v4 = val;
        }
        out_ui[(size_t)899 * NP_] = v4;
        u0 = v0; u1 = v1; u2 = v2; u3 = v3; u4 = v4;
    }
    {
        float pf0 = CF(999), pf1 = CF(998), pf2 = CF(997), pf3 = CF(996), pf4 = CF(995);
        // peel q=5..10 (j=898..893): weights 0,0,7,32,12,32
        PEEL_STEP(CF(994), out_ui + (size_t)898*NP_, W0 );
        PEEL_STEP(CF(993), out_ui + (size_t)897*NP_, W0 );
        PEEL_STEP(CF(992), out_ui + (size_t)896*NP_, W7 );
        PEEL_STEP(CF(991), out_ui + (size_t)895*NP_, W32);
        PEEL_STEP(CF(990), out_ui + (size_t)894*NP_, W12);
        PEEL_STEP(CF(989), out_ui + (size_t)893*NP_, W32);
        // lanes for steady groups starting q0=11: rev indices 7..14 -> CF(992..985)
        float f0 = pf1, f1 = pf2, f2 = pf3, f3 = pf4;
        float f4 = CF(988), f5 = CF(987), f6 = CF(986), f7 = CF(985);
        float a0 = R1c*f0, a1 = R1c*f1, a2 = R1c*f2, a3 = R1c*f3;
        float a4 = R1c*f4, a5 = R1c*f5, a6 = R1c*f6, a7 = R1c*f7;
        float b0 = R2c*f0, b1 = R2c*f1, b2 = R2c*f2, b3 = R2c*f3;
        float b4 = R2c*f4, b5 = R2c*f5, b6 = R2c*f6, b7 = R2c*f7;
        (void)a0; (void)b0; (void)b1;

        float* pr = out_ui + (size_t)889 * NP_;   // group stores j at +3NP,+2NP,+NP,+0
        int ri = 984;
        #pragma unroll 1
        for (int g = 0; g < 222; ++g) {
            float n0 = CF(ri), n1 = CF(ri-1), n2 = CF(ri-2), n3 = CF(ri-3);
            ri -= 4;
            float na0 = R1c*n0, na1 = R1c*n1, na2 = R1c*n2, na3 = R1c*n3;
            float nb0 = R2c*n0, nb1 = R2c*n1, nb2 = R2c*n2, nb3 = R2c*n3;
            float e0 = f4+1.0f, g0_ = fmaf(f4,f4,1.0f), r0 = e0*g0_;
            float e1 = f5+1.0f, g1_ = fmaf(f5,f5,1.0f), r1 = e1*g1_;
            float e2 = f6+1.0f, g2_ = fmaf(f6,f6,1.0f), r2 = e2*g2_;
            float e3 = f7+1.0f, g3_ = fmaf(f7,f7,1.0f), r3 = e3*g3_;
            DOT_STEP(f0, a1, b2, a3, r0, pr + 3*(size_t)NP_, W14);
            DOT_STEP(f1, a2, b3, a4, r1, pr + 2*(size_t)NP_, W32);
            DOT_STEP(f2, a3, b4, a5, r2, pr + NP_,           W12);
            DOT_STEP(f3, a4, b5, a6, r3, pr,                 W32);
            f0 = f4; f1 = f5; f2 = f6; f3 = f7; f4 = n0; f5 = n1; f6 = n2; f7 = n3;
            a1 = a5; a2 = a6; a3 = a7; a4 = na0; a5 = na1; a6 = na2; a7 = na3;
            b2 = b6; b3 = b7; b4 = nb0; b5 = nb1; b6 = nb2; b7 = nb3;
            pr -= 4 * (size_t)NP_;
        }
    }
    // final window -> u_infty[0..4]
    out_ui[0]               = u0;
    out_ui[(size_t)1 * NP_] = u1;
    out_ui[(size_t)2 * NP_] = u2;
    out_ui[(size_t)3 * NP_] = u3;
    out_ui[(size_t)4 * NP_] = u4;
    {
        float q0 = u0*u0, q1 = u1*u1, q2 = u2*u2, q3 = u3*u3, q4 = u4*u4;
        acc4 += 7.0f*(q0*q0) + 32.0f*(q1*q1) + 32.0f*(q3*q3) + 14.0f*(q4*q4);
        acc2 += 12.0f*q2;
        float dnr = (25.0f*u0 - 48.0f*u1 + 36.0f*u2 - 16.0f*u3 + 3.0f*u4) * DRCP;
        float integ_out = (acc4 + acc2) * WINT;
        float s_out = integ_out / (u0 * u0);

        // delta combine: mirror-energy derivative from paired lane
        float dnm = __shfl_xor_sync(0xffffffffu, dnr, 1);
        float lfo = dnm / u0;
        float delta = -(lfo - lfin) / (s_in + s_out);
        out[idx] = E + delta;
    }
    #undef DOT_STEP
    #undef PEEL_STEP
    #undef CF
}

extern "C" void kernel_launch(void* const* d_in, const int* in_sizes, int n_in,
                              void* d_out, int out_size) {
    const float* init_energy = (const float*)d_in[0];
    float* out = (float*)d_out;
    (void)in_sizes; (void)n_in; (void)out_size;
    eval_kernel<<<NP_ / 128, 128>>>(init_energy, out);
}

// round 5
// speedup vs baseline: 9.3112x; 1.0064x over previous
#include <cuda_runtime.h>

#define NE_ 4096
#define NP_ 12288

__global__ void __launch_bounds__(128) eval_kernel(const float* __restrict__ energy_in,
                                                   float* __restrict__ out) {
    // per-l radial table with C folded: s_g[l][i] = C*(l(l+1)/r^2 - 1/r), r = 0.1*(i+1)
    __shared__ float s_g[3 * 1000];
    {
        const float C = 7.5e-4f;   // 3/40 * 0.1^2
        for (int i = threadIdx.x; i < 1000; i += 128) {
            float r   = fmaf((float)i, 0.1f, 0.1f);
            float y   = 1.0f / r;           // precise, amortized
            float cy  = C * y;
            float cy2 = cy * y;
            s_g[i]        = -cy;
            s_g[1000 + i] = fmaf(2.0f, cy2, -cy);
            s_g[2000 + i] = fmaf(6.0f, cy2, -cy);
        }
    }
    __syncthreads();

    // lane pairing: tau and tau^1 handle mirror energies (e, NE-1-e), same l
    int tau = blockIdx.x * 128 + threadIdx.x;
    int h   = tau >> 1;
    int s_  = tau & 1;
    int ep  = h / 3;
    int l   = h - ep * 3;
    int e   = s_ ? (NE_ - 1 - ep) : ep;
    int idx = e * 3 + l;

    float E  = energy_in[e];
    float lf = (float)l;
    const float C = 7.5e-4f;
    float CE = C * E;
    const float* gl = &s_g[l * 1000];
    #define CF(i) (gl[(i)] - CE)

    const float R1c  = (float)(104.0 / 9.0);   // (13/15*d^2)/C
    const float R2c  = (float)(14.0 / 9.0);    // (7/60*d^2)/C
    const float WINT = (float)(2.0 * 0.1 / 45.0);
    const float DRCP = (float)(1.0 / 1.2);

    float* out_uz = out + NP_ + idx;
    float* out_ui = out + NP_ + (size_t)100 * NP_ + idx;

    float u0, u1, u2, u3, u4;
    float acc4, acc2;

    // one step: nv = ka*u1+kb*u2+kc*u3+kd*u4, rden = rcp(1-w4)
    #define DOT_STEP(V0,V1,V2,V3,V4, STADDR, WCODE) do {          \
        float rd; { float dd = 1.0f - (V4);                       \
            asm("rcp.approx.f32 %0, %1;" : "=f"(rd) : "f"(dd)); } \
        float ka = fmaf((V0),       rd, -1.0f);                   \
        float kb = fmaf(R1c*(V1),   rd,  2.0f);                   \
        float kc = fmaf(R2c*(V2),   rd, -2.0f);                   \
        float kd = fmaf(R1c*(V3),   rd,  2.0f);                   \
        float tt = ka * u1;                                       \
        tt = fmaf(kb, u2, tt);                                    \
        tt = fmaf(kc, u3, tt);                                    \
        float nv = fmaf(kd, u4, tt);                              \
        *(STADDR) = nv;                                           \
        { float q = nv * nv; WCODE; }                             \
        u0 = u1; u1 = u2; u2 = u3; u3 = u4; u4 = nv;              \
    } while (0)

    #define W14 { float qq = q*q; acc4 = fmaf(14.0f, qq, acc4); }
    #define W32 { float qq = q*q; acc4 = fmaf(32.0f, qq, acc4); }
    #define W12 { acc2 = fmaf(12.0f, q, acc2); }
    #define W7  { float qq = q*q; acc4 = fmaf(7.0f,  qq, acc4); }
    #define W0  { (void)q; }

    #define PEEL_STEP(NEWCF, STADDR, WCODE) do {                  \
        float fn = (NEWCF);                                       \
        pf0 = pf1; pf1 = pf2; pf2 = pf3; pf3 = pf4; pf4 = fn;     \
        DOT_STEP(pf0, pf1, pf2, pf3, pf4, STADDR, WCODE);         \
    } while (0)

    float lfin, s_in;

    // ======================= forward: u_zero (100 pts) =======================
    {
        float v0, v1, v2, v3, v4;
        {
            float inv2l1 = 1.0f / (2.0f * (lf + 1.0f));
            #pragma unroll
            for (int j = 0; j < 5; ++j) {
                float r0 = 0.1f * (float)(j + 1);
                float p1 = r0;
                if (l >= 1) p1 *= r0;
                if (l >= 2) p1 *= r0;
                float val = p1 - (p1 * r0) * inv2l1;
                out_uz[(size_t)j * NP_] = val;
                if (j == 0) v0 = val; else if (j == 1) v1 = val;
                else if (j == 2) v2 = val; else if (j == 3) v3 = val; else v4 = val;
            }
        }
        out_uz[(size_t)5 * NP_] = v4;   // duplicated window point
        float q0 = v0*v0, q1 = v1*v1, q2 = v2*v2, q3 = v3*v3, q4 = v4*v4;
        acc4 = 7.0f*q0*q0 + 32.0f*q1*q1 + 32.0f*q3*q3 + 14.0f*q4*q4 + 32.0f*q4*q4;
        acc2 = 12.0f*q2;
        u0 = v0; u1 = v1; u2 = v2; u3 = v3; u4 = v4;
    }

    {
        float pf0 = CF(0), pf1 = CF(1), pf2 = CF(2), pf3 = CF(3), pf4 = CF(4);
        // peel p=5..10 (j=6..11): weights 12,32,14,32,12,32
        PEEL_STEP(CF(5),  out_uz + (size_t)6*NP_,  W12);
        PEEL_STEP(CF(6),  out_uz + (size_t)7*NP_,  W32);
        PEEL_STEP(CF(7),  out_uz + (size_t)8*NP_,  W14);
        PEEL_STEP(CF(8),  out_uz + (size_t)9*NP_,  W32);
        PEEL_STEP(CF(9),  out_uz + (size_t)10*NP_, W12);
        PEEL_STEP(CF(10), out_uz + (size_t)11*NP_, W32);

        // steady state: window f0..f7 = cf(7..14) at p0=11
        float f0 = CF(7),  f1 = CF(8),  f2 = CF(9),  f3 = CF(10);
        float f4 = CF(11), f5 = CF(12), f6 = CF(13), f7 = CF(14);

        float* pfp = out_uz + (size_t)12 * NP_;
        int pi = 15;
        #pragma unroll 1
        for (int g = 0; g < 11; ++g) {   // 11 x 8 = 88 steps, p=11..98
            float n0 = CF(pi), n1 = CF(pi+1), n2 = CF(pi+2), n3 = CF(pi+3);
            DOT_STEP(f0,f1,f2,f3,f4, pfp,                 W14);
            DOT_STEP(f1,f2,f3,f4,f5, pfp + NP_,           W32);
            DOT_STEP(f2,f3,f4,f5,f6, pfp + 2*(size_t)NP_, W12);
            DOT_STEP(f3,f4,f5,f6,f7, pfp + 3*(size_t)NP_, W32);
            float n4 = CF(pi+4), n5 = CF(pi+5), n6 = CF(pi+6), n7 = CF(pi+7);
            DOT_STEP(f4,f5,f6,f7,n0, pfp + 4*(size_t)NP_, W14);
            DOT_STEP(f5,f6,f7,n0,n1, pfp + 5*(size_t)NP_, W32);
            DOT_STEP(f6,f7,n0,n1,n2, pfp + 6*(size_t)NP_, W12);
            DOT_STEP(f7,n0,n1,n2,n3, pfp + 7*(size_t)NP_, W32);
            f0 = n0; f1 = n1; f2 = n2; f3 = n3;
            f4 = n4; f5 = n5; f6 = n6; f7 = n7;
            pi  += 8;
            pfp += 8 * (size_t)NP_;
        }
    }
    // end state u0..u4 = j95..99
    {
        float dnf = (25.0f*u4 - 48.0f*u3 + 36.0f*u2 - 16.0f*u1 + 3.0f*u0) * DRCP;
        lfin = dnf / u4;
        // corrections: j96 14->7; j97/j98/j99 excluded
        float q1 = u1*u1, q2 = u2*u2, q3 = u3*u3, q4 = u4*u4;
        acc4 -= 7.0f*(q1*q1) + 32.0f*(q2*q2) + 32.0f*(q4*q4);
        acc2 -= 12.0f*q3;
        float integ_in = (acc4 + acc2) * WINT;
        s_in = integ_in / (u4 * u4);
    }

    // ======================= reverse: u_infty (900 pts) =======================
    acc4 = 0.0f; acc2 = 0.0f;
    {
        float fact_l = (l == 0) ? 1.0f : ((l == 1) ? 3.0f : 15.0f);
        float se = sqrtf(fabsf(E));
        float i3  = 1.0f / (2.0f*lf + 3.0f);
        float i35 = 1.0f / (2.0f*(2.0f*lf + 3.0f)*(2.0f*lf + 5.0f));
        float v0, v1, v2, v3, v4;
        #pragma unroll
        for (int j = 0; j < 5; ++j) {
            float rj = (float)(99.6 + 0.1 * (double)j);
            float x  = rj * se;
            float xl = 1.0f;
            if (l >= 1) xl *= x;
            if (l >= 2) xl *= x;
            float base = xl / fact_l;
            float x2h  = (x*x) * 0.5f;
            float t1 = x2h * i3;
            float t2 = (x2h*x2h) * i35;
            float val = rj * (base * (1.0f + t1 + t2));
            if (j == 0) v0 = val; else if (j == 1) v1 = val;
            else if (j == 2) v2 = val; else if (j == 3) v3 = val; else v4 = val;
        }
        out_ui[(size_t)899 * NP_] = v4;
        u0 = v0; u1 = v1; u2 = v2; u3 = v3; u4 = v4;
    }
    {
        float pf0 = CF(999), pf1 = CF(998), pf2 = CF(997), pf3 = CF(996), pf4 = CF(995);
        // peel q=5..10 (j=898..893): weights 0,0,7,32,12,32
        PEEL_STEP(CF(994), out_ui + (size_t)898*NP_, W0 );
        PEEL_STEP(CF(993), out_ui + (size_t)897*NP_, W0 );
        PEEL_STEP(CF(992), out_ui + (size_t)896*NP_, W7 );
        PEEL_STEP(CF(991), out_ui + (size_t)895*NP_, W32);
        PEEL_STEP(CF(990), out_ui + (size_t)894*NP_, W12);
        PEEL_STEP(CF(989), out_ui + (size_t)893*NP_, W32);

        // steady: window f0..f7 = cf_rev(7..14) = CF(992..985) at q0=11
        float f0 = CF(992), f1 = CF(991), f2 = CF(990), f3 = CF(989);
        float f4 = CF(988), f5 = CF(987), f6 = CF(986), f7 = CF(985);

        // iteration i stores j = 892-8i .. 885-8i at pr+7NP .. pr, pr = (885-8i)NP
        float* pr = out_ui + (size_t)885 * NP_;
        int ri = 984;
        #pragma unroll 1
        for (int g = 0; g < 111; ++g) {  // 111 x 8 = 888 steps, q=11..898
            float n0 = CF(ri), n1 = CF(ri-1), n2 = CF(ri-2), n3 = CF(ri-3);
            DOT_STEP(f0,f1,f2,f3,f4, pr + 7*(size_t)NP_, W14);
            DOT_STEP(f1,f2,f3,f4,f5, pr + 6*(size_t)NP_, W32);
            DOT_STEP(f2,f3,f4,f5,f6, pr + 5*(size_t)NP_, W12);
            DOT_STEP(f3,f4,f5,f6,f7, pr + 4*(size_t)NP_, W32);
            float n4 = CF(ri-4), n5 = CF(ri-5), n6 = CF(ri-6), n7 = CF(ri-7);
            DOT_STEP(f4,f5,f6,f7,n0, pr + 3*(size_t)NP_, W14);
            DOT_STEP(f5,f6,f7,n0,n1, pr + 2*(size_t)NP_, W32);
            DOT_STEP(f6,f7,n0,n1,n2, pr + NP_,           W12);
            DOT_STEP(f7,n0,n1,n2,n3, pr,                 W32);
            f0 = n0; f1 = n1; f2 = n2; f3 = n3;
            f4 = n4; f5 = n5; f6 = n6; f7 = n7;
            ri -= 8;
            pr -= 8 * (size_t)NP_;
        }
    }
    // final window -> u_infty[0..4]
    out_ui[0]               = u0;
    out_ui[(size_t)1 * NP_] = u1;
    out_ui[(size_t)2 * NP_] = u2;
    out_ui[(size_t)3 * NP_] = u3;
    out_ui[(size_t)4 * NP_] = u4;
    {
        float q0 = u0*u0, q1 = u1*u1, q2 = u2*u2, q3 = u3*u3, q4 = u4*u4;
        acc4 += 7.0f*(q0*q0) + 32.0f*(q1*q1) + 32.0f*(q3*q3) + 14.0f*(q4*q4);
        acc2 += 12.0f*q2;
        float dnr = (25.0f*u0 - 48.0f*u1 + 36.0f*u2 - 16.0f*u3 + 3.0f*u4) * DRCP;
        float integ_out = (acc4 + acc2) * WINT;
        float s_out = integ_out / (u0 * u0);

        // delta combine: mirror-energy derivative from paired lane
        float dnm = __shfl_xor_sync(0xffffffffu, dnr, 1);
        float lfo = dnm / u0;
        float delta = -(lfo - lfin) / (s_in + s_out);
        out[idx] = E + delta;
    }
    #undef DOT_STEP
    #undef PEEL_STEP
    #undef CF
}

extern "C" void kernel_launch(void* const* d_in, const int* in_sizes, int n_in,
                              void* d_out, int out_size) {
    const float* init_energy = (const float*)d_in[0];
    float* out = (float*)d_out;
    (void)in_sizes; (void)n_in; (void)out_size;
    eval_kernel<<<NP_ / 128, 128>>>(init_energy, out);
}

// round 8
// speedup vs baseline: 10.1389x; 1.0889x over previous
#include <cuda_runtime.h>

#define NE_ 4096
#define NP_ 12288

__global__ void __launch_bounds__(128) eval_kernel(const float* __restrict__ energy_in,
                                                   float* __restrict__ out) {
    // per-l radial table with C folded: s_g[l][i] = C*(l(l+1)/r^2 - 1/r), r = 0.1*(i+1)
    __shared__ float s_g[3 * 1000];
    {
        const float C = 7.5e-4f;   // 3/40 * 0.1^2
        for (int i = threadIdx.x; i < 1000; i += 128) {
            float r   = fmaf((float)i, 0.1f, 0.1f);
            float y   = 1.0f / r;           // precise, amortized
            float cy  = C * y;
            float cy2 = cy * y;
            s_g[i]        = -cy;
            s_g[1000 + i] = fmaf(2.0f, cy2, -cy);
            s_g[2000 + i] = fmaf(6.0f, cy2, -cy);
        }
    }
    __syncthreads();

    // lane pairing: tau and tau^1 handle mirror energies (e, NE-1-e), same l
    int tau = blockIdx.x * 128 + threadIdx.x;
    int h   = tau >> 1;
    int s_  = tau & 1;
    int ep  = h / 3;
    int l   = h - ep * 3;
    int e   = s_ ? (NE_ - 1 - ep) : ep;
    int idx = e * 3 + l;

    float E  = energy_in[e];
    float lf = (float)l;
    const float C = 7.5e-4f;
    float CE = C * E;
    const float* gl = &s_g[l * 1000];
    #define CF(i) (gl[(i)] - CE)

    const float R1c  = (float)(104.0 / 9.0);   // (13/15*d^2)/C
    const float R2c  = (float)(14.0 / 9.0);    // (7/60*d^2)/C
    const float WINT = (float)(2.0 * 0.1 / 45.0);
    const float DRCP = (float)(1.0 / 1.2);
    volatile float onef_v = 1.0f;              // keep 1.0 in a register for imm-fma dd
    float onef = onef_v;

    float* out_uz = out + NP_ + idx;
    float* out_ui = out + NP_ + (size_t)100 * NP_ + idx;

    float u0, u1, u2, u3, u4;
    float acc4, acc2;

    // split-form step (R3 structure, passed): nv = rd*sv + base
    //   sv   = V0*u1 + R1c*(V1*u2 + V3*u4) + R2c*(V2*u3)   (R1c/R2c as imm-fma)
    //   base = 2*u2 - u1 - 2*u3 + 2*u4                      (3 imm-fma)
    //   rd   = rcp.approx(1 - V4)                           (dd as imm-fma)
    #define DOT_STEP(V0,V1,V2,V3,V4, STADDR, WCODE) do {          \
        float dd = fmaf(-1.0f, (V4), onef);                       \
        float rd; asm("rcp.approx.f32 %0, %1;" : "=f"(rd) : "f"(dd)); \
        float t1 = (V1) * u2;  t1 = fmaf((V3), u4, t1);           \
        float r3 = (V2) * u3;                                     \
        float t2 = (V0) * u1;  t2 = fmaf(R2c, r3, t2);            \
        float sv = fmaf(R1c, t1, t2);                             \
        float bs = fmaf(2.0f, u2, -u1);                           \
        bs = fmaf(-2.0f, u3, bs);                                 \
        bs = fmaf(2.0f, u4, bs);                                  \
        float nv = fmaf(rd, sv, bs);                              \
        *(STADDR) = nv;                                           \
        { float q = nv * nv; WCODE; }                             \
        u0 = u1; u1 = u2; u2 = u3; u3 = u4; u4 = nv;              \
    } while (0)

    #define W14 { float qq = q*q; acc4 = fmaf(14.0f, qq, acc4); }
    #define W32 { float qq = q*q; acc4 = fmaf(32.0f, qq, acc4); }
    #define W12 { acc2 = fmaf(12.0f, q, acc2); }
    #define W7  { float qq = q*q; acc4 = fmaf(7.0f,  qq, acc4); }
    #define W0  { (void)q; }

    #define PEEL_STEP(NEWCF, STADDR, WCODE) do {                  \
        float fn = (NEWCF);                                       \
        pf0 = pf1; pf1 = pf2; pf2 = pf3; pf3 = pf4; pf4 = fn;     \
        DOT_STEP(pf0, pf1, pf2, pf3, pf4, STADDR, WCODE);         \
    } while (0)

    float lfin, s_in;

    // ======================= forward: u_zero (100 pts) =======================
    {
        float v0, v1, v2, v3, v4;
        {
            float inv2l1 = 1.0f / (2.0f * (lf + 1.0f));
            #pragma unroll
            for (int j = 0; j < 5; ++j) {
                float r0 = 0.1f * (float)(j + 1);
                float p1 = r0;
                if (l >= 1) p1 *= r0;
                if (l >= 2) p1 *= r0;
                float val = p1 - (p1 * r0) * inv2l1;
                out_uz[(size_t)j * NP_] = val;
                if (j == 0) v0 = val; else if (j == 1) v1 = val;
                else if (j == 2) v2 = val; else if (j == 3) v3 = val; else v4 = val;
            }
        }
        out_uz[(size_t)5 * NP_] = v4;   // duplicated window point
        float q0 = v0*v0, q1 = v1*v1, q2 = v2*v2, q3 = v3*v3, q4 = v4*v4;
        acc4 = 7.0f*q0*q0 + 32.0f*q1*q1 + 32.0f*q3*q3 + 14.0f*q4*q4 + 32.0f*q4*q4;
        acc2 = 12.0f*q2;
        u0 = v0; u1 = v1; u2 = v2; u3 = v3; u4 = v4;
    }

    {
        float pf0 = CF(0), pf1 = CF(1), pf2 = CF(2), pf3 = CF(3), pf4 = CF(4);
        // peel p=5..10 (j=6..11): weights 12,32,14,32,12,32
        PEEL_STEP(CF(5),  out_uz + (size_t)6*NP_,  W12);
        PEEL_STEP(CF(6),  out_uz + (size_t)7*NP_,  W32);
        PEEL_STEP(CF(7),  out_uz + (size_t)8*NP_,  W14);
        PEEL_STEP(CF(8),  out_uz + (size_t)9*NP_,  W32);
        PEEL_STEP(CF(9),  out_uz + (size_t)10*NP_, W12);
        PEEL_STEP(CF(10), out_uz + (size_t)11*NP_, W32);

        // steady state: window f0..f7 = cf(7..14) at p0=11
        float f0 = CF(7),  f1 = CF(8),  f2 = CF(9),  f3 = CF(10);
        float f4 = CF(11), f5 = CF(12), f6 = CF(13), f7 = CF(14);

        float* pfp = out_uz + (size_t)12 * NP_;
        int pi = 15;
        #pragma unroll 1
        for (int g = 0; g < 11; ++g) {   // 11 x 8 = 88 steps, p=11..98
            float n0 = CF(pi), n1 = CF(pi+1), n2 = CF(pi+2), n3 = CF(pi+3);
            DOT_STEP(f0,f1,f2,f3,f4, pfp,                 W14);
            DOT_STEP(f1,f2,f3,f4,f5, pfp + NP_,           W32);
            DOT_STEP(f2,f3,f4,f5,f6, pfp + 2*(size_t)NP_, W12);
            DOT_STEP(f3,f4,f5,f6,f7, pfp + 3*(size_t)NP_, W32);
            float n4 = CF(pi+4), n5 = CF(pi+5), n6 = CF(pi+6), n7 = CF(pi+7);
            DOT_STEP(f4,f5,f6,f7,n0, pfp + 4*(size_t)NP_, W14);
            DOT_STEP(f5,f6,f7,n0,n1, pfp + 5*(size_t)NP_, W32);
            DOT_STEP(f6,f7,n0,n1,n2, pfp + 6*(size_t)NP_, W12);
            DOT_STEP(f7,n0,n1,n2,n3, pfp + 7*(size_t)NP_, W32);
            f0 = n0; f1 = n1; f2 = n2; f3 = n3;
            f4 = n4; f5 = n5; f6 = n6; f7 = n7;
            pi  += 8;
            pfp += 8 * (size_t)NP_;
        }
    }
    // end state u0..u4 = j95..99
    {
        float dnf = (25.0f*u4 - 48.0f*u3 + 36.0f*u2 - 16.0f*u1 + 3.0f*u0) * DRCP;
        lfin = dnf / u4;
        // corrections: j96 14->7; j97/j98/j99 excluded
        float q1 = u1*u1, q2 = u2*u2, q3 = u3*u3, q4 = u4*u4;
        acc4 -= 7.0f*(q1*q1) + 32.0f*(q2*q2) + 32.0f*(q4*q4);
        acc2 -= 12.0f*q3;
        float integ_in = (acc4 + acc2) * WINT;
        s_in = integ_in / (u4 * u4);
    }

    // ======================= reverse: u_infty (900 pts) =======================
    acc4 = 0.0f; acc2 = 0.0f;
    {
        float fact_l = (l == 0) ? 1.0f : ((l == 1) ? 3.0f : 15.0f);
        float se = sqrtf(fabsf(E));
        float i3  = 1.0f / (2.0f*lf + 3.0f);
        float i35 = 1.0f / (2.0f*(2.0f*lf + 3.0f)*(2.0f*lf + 5.0f));
        float v0, v1, v2, v3, v4;
        #pragma unroll
        for (int j = 0; j < 5; ++j) {
            float rj = (float)(99.6 + 0.1 * (double)j);
            float xx = rj * se;
            float xl = 1.0f;
            if (l >= 1) xl *= xx;
            if (l >= 2) xl *= xx;
            float base = xl / fact_l;
            float x2h  = (xx*xx) * 0.5f;
            float t1 = x2h * i3;
            float t2 = (x2h*x2h) * i35;
            float val = rj * (base * (1.0f + t1 + t2));
            if (j == 0) v0 = val; else if (j == 1) v1 = val;
            else if (j == 2) v2 = val; else if (j == 3) v3 = val; else v4 = val;
        }
        out_ui[(size_t)899 * NP_] = v4;
        u0 = v0; u1 = v1; u2 = v2; u3 = v3; u4 = v4;
    }
    {
        float pf0 = CF(999), pf1 = CF(998), pf2 = CF(997), pf3 = CF(996), pf4 = CF(995);
        // peel q=5..10 (j=898..893): weights 0,0,7,32,12,32
        PEEL_STEP(CF(994), out_ui + (size_t)898*NP_, W0 );
        PEEL_STEP(CF(993), out_ui + (size_t)897*NP_, W0 );
        PEEL_STEP(CF(992), out_ui + (size_t)896*NP_, W7 );
        PEEL_STEP(CF(991), out_ui + (size_t)895*NP_, W32);
        PEEL_STEP(CF(990), out_ui + (size_t)894*NP_, W12);
        PEEL_STEP(CF(989), out_ui + (size_t)893*NP_, W32);

        // steady: window f0..f7 = cf_rev(7..14) = CF(992..985) at q0=11
        float f0 = CF(992), f1 = CF(991), f2 = CF(990), f3 = CF(989);
        float f4 = CF(988), f5 = CF(987), f6 = CF(986), f7 = CF(985);

        // iteration i stores j = 892-8i .. 885-8i at pr+7NP .. pr, pr = (885-8i)NP
        float* pr = out_ui + (size_t)885 * NP_;
        int ri = 984;
        #pragma unroll 1
        for (int g = 0; g < 111; ++g) {  // 111 x 8 = 888 steps, q=11..898
            float n0 = CF(ri), n1 = CF(ri-1), n2 = CF(ri-2), n3 = CF(ri-3);
            DOT_STEP(f0,f1,f2,f3,f4, pr + 7*(size_t)NP_, W14);
            DOT_STEP(f1,f2,f3,f4,f5, pr + 6*(size_t)NP_, W32);
            DOT_STEP(f2,f3,f4,f5,f6, pr + 5*(size_t)NP_, W12);
            DOT_STEP(f3,f4,f5,f6,f7, pr + 4*(size_t)NP_, W32);
            float n4 = CF(ri-4), n5 = CF(ri-5), n6 = CF(ri-6), n7 = CF(ri-7);
            DOT_STEP(f4,f5,f6,f7,n0, pr + 3*(size_t)NP_, W14);
            DOT_STEP(f5,f6,f7,n0,n1, pr + 2*(size_t)NP_, W32);
            DOT_STEP(f6,f7,n0,n1,n2, pr + NP_,           W12);
            DOT_STEP(f7,n0,n1,n2,n3, pr,                 W32);
            f0 = n0; f1 = n1; f2 = n2; f3 = n3;
            f4 = n4; f5 = n5; f6 = n6; f7 = n7;
            ri -= 8;
            pr -= 8 * (size_t)NP_;
        }
    }
    // final window -> u_infty[0..4]
    out_ui[0]               = u0;
    out_ui[(size_t)1 * NP_] = u1;
    out_ui[(size_t)2 * NP_] = u2;
    out_ui[(size_t)3 * NP_] = u3;
    out_ui[(size_t)4 * NP_] = u4;
    {
        float q0 = u0*u0, q1 = u1*u1, q2 = u2*u2, q3 = u3*u3, q4 = u4*u4;
        acc4 += 7.0f*(q0*q0) + 32.0f*(q1*q1) + 32.0f*(q3*q3) + 14.0f*(q4*q4);
        acc2 += 12.0f*q2;
        float dnr = (25.0f*u0 - 48.0f*u1 + 36.0f*u2 - 16.0f*u3 + 3.0f*u4) * DRCP;
        float integ_out = (acc4 + acc2) * WINT;
        float s_out = integ_out / (u0 * u0);

        // delta combine: mirror-energy derivative from paired lane
        float dnm = __shfl_xor_sync(0xffffffffu, dnr, 1);
        float lfo = dnm / u0;
        float delta = -(lfo - lfin) / (s_in + s_out);
        out[idx] = E + delta;
    }
    #undef DOT_STEP
    #undef PEEL_STEP
    #undef CF
}

extern "C" void kernel_launch(void* const* d_in, const int* in_sizes, int n_in,
                              void* d_out, int out_size) {
    const float* init_energy = (const float*)d_in[0];
    float* out = (float*)d_out;
    (void)in_sizes; (void)n_in; (void)out_size;
    eval_kernel<<<NP_ / 128, 128>>>(init_energy, out);
}